// round 11
// baseline (speedup 1.0000x reference)
#include <cuda_runtime.h>
#include <cuda_bf16.h>
#include <cstdint>

#define NN 512
using bf16 = __nv_bfloat16;

// ---------------------------------------------------------------------------
// Device scratch (no allocation allowed)
// ---------------------------------------------------------------------------
#define DECLB(n) __device__ __align__(16) bf16 n[NN * NN]
DECLB(g_Xhi);   DECLB(g_Xlo);
DECLB(g_W1Thi); DECLB(g_W1Tlo);
DECLB(g_W2Thi); DECLB(g_W2Tlo);
DECLB(g_W2hi);  DECLB(g_W2lo);
DECLB(g_H1hi);  DECLB(g_H1lo);
DECLB(g_H2hi);  DECLB(g_H2lo);
DECLB(g_G1hi);  DECLB(g_G1lo);
DECLB(g_G2hi);  DECLB(g_G2lo);
__device__ __align__(16) float g_Fb[4][NN * NN];     // fwd k-split banks
__device__ __align__(16) float g_GPb[20][NN * NN];   // gram banks [matrix*4+z]
__device__ int g_CntF[128];   // fwd per-tile counters (self-resetting)
__device__ int g_CntG[72];    // gram per-tile counters (self-resetting)

// ---------------------------------------------------------------------------
// PTX helpers (base PTX only — valid on virtual target sm_103)
// ---------------------------------------------------------------------------
__device__ __forceinline__ uint32_t smem_u32(const void* p) {
    return (uint32_t)__cvta_generic_to_shared(p);
}
__device__ __forceinline__ void ldm_x4(uint32_t a[4], uint32_t addr) {
    asm volatile("ldmatrix.sync.aligned.m8n8.x4.shared.b16 {%0,%1,%2,%3}, [%4];"
                 : "=r"(a[0]), "=r"(a[1]), "=r"(a[2]), "=r"(a[3]) : "r"(addr));
}
__device__ __forceinline__ void mma_bf16(float c[4], const uint32_t a[4],
                                         const uint32_t b[2]) {
    asm volatile(
        "mma.sync.aligned.m16n8k16.row.col.f32.bf16.bf16.f32 "
        "{%0,%1,%2,%3}, {%4,%5,%6,%7}, {%8,%9}, {%0,%1,%2,%3};"
        : "+f"(c[0]), "+f"(c[1]), "+f"(c[2]), "+f"(c[3])
        : "r"(a[0]), "r"(a[1]), "r"(a[2]), "r"(a[3]), "r"(b[0]), "r"(b[1]));
}
__device__ __forceinline__ void cp16(uint32_t dst, const void* src) {
    asm volatile("cp.async.cg.shared.global [%0], [%1], 16;" :: "r"(dst), "l"(src));
}
__device__ __forceinline__ void red_add(float* p, float v) {
    asm volatile("red.global.add.f32 [%0], %1;" :: "l"(p), "f"(v) : "memory");
}
#define CP_COMMIT() asm volatile("cp.async.commit_group;" ::: "memory")
#define CP_WAIT0()  asm volatile("cp.async.wait_group 0;" ::: "memory")
#define CP_WAIT1()  asm volatile("cp.async.wait_group 1;" ::: "memory")

__device__ __forceinline__ void split_store(bf16* hi, bf16* lo, int off, float v) {
    bf16 h = __float2bfloat16(v);
    hi[off] = h;
    lo[off] = __float2bfloat16(v - __bfloat162float(h));
}

// Last-CTA-per-tile gate (every thread of the CTA must call).
__device__ __forceinline__ bool last_of(int* cnt, int target) {
    __threadfence();
    __shared__ int lastFlag;
    if (threadIdx.x == 0) lastFlag = (atomicAdd(cnt, 1) == target - 1) ? 1 : 0;
    __syncthreads();
    if (!lastFlag) return false;
    __threadfence();
    return true;
}

// ===========================================================================
// Uniform GEMM job: tile M=64, N=32, K=128 (4 k32 stages), 128 threads,
// 4 warps (4m), warp tile 16x32 => 4 m16n8 accumulator fragments (ILP 4).
// SMEM ring of 3 stages. Stage layout (bytes):
//   Ahi[2sub][64][24h]@0 (6144), Alo@6144, Bhi[2][32][24h]@12288 (3072),
//   Blo@15360. Stage stride 18432. Ring total 55296 -> 4 CTAs/SM.
// ===========================================================================
constexpr int Q_SUBA  = 3072;    // 64 rows * 48 B (one k16 sub-slice of A)
constexpr int Q_SUBB  = 1536;    // 32 rows * 48 B (one k16 sub-slice of B)
constexpr int Q_ALO   = 6144;
constexpr int Q_BHI   = 12288;
constexpr int Q_BLO   = 15360;
constexpr int Q_STAGE = 18432;
constexpr int Q_SMEM  = 3 * Q_STAGE;   // 55296

__device__ __forceinline__ void mainloop_q(
    const bf16* __restrict__ Ahi, const bf16* __restrict__ Alo,
    const bf16* __restrict__ Bhi, const bf16* __restrict__ Blo,
    int rowBase, int colBase, int kBase, uint32_t sb, float acc[4][4])
{
    const int t = threadIdx.x;
    const int lane = t & 31, wm = t >> 5;

    // cp.async mapping: per thread per stage: 2 A-hi, 2 A-lo, 1 B-hi, 1 B-lo
    const int a0r = t >> 2, ac = t & 3;
    const int a1r = 32 + a0r;
    const uint32_t dA0 = (uint32_t)((ac >> 1) * Q_SUBA + a0r * 48 + (ac & 1) * 16);
    const uint32_t dA1 = (uint32_t)((ac >> 1) * Q_SUBA + a1r * 48 + (ac & 1) * 16);
    const uint32_t dB  = (uint32_t)((ac >> 1) * Q_SUBB + a0r * 48 + (ac & 1) * 16);
    const bf16* pA0h = Ahi + (rowBase + a0r) * NN + kBase + ac * 8;
    const bf16* pA0l = Alo + (rowBase + a0r) * NN + kBase + ac * 8;
    const bf16* pA1h = Ahi + (rowBase + a1r) * NN + kBase + ac * 8;
    const bf16* pA1l = Alo + (rowBase + a1r) * NN + kBase + ac * 8;
    const bf16* pBh  = Bhi + (colBase + a0r) * NN + kBase + ac * 8;
    const bf16* pBl  = Blo + (colBase + a0r) * NN + kBase + ac * 8;

    auto issue = [&](int stg) {
        const uint32_t base = sb + (stg % 3) * Q_STAGE;
        const int k0 = stg * 32;
        cp16(base + dA0,         pA0h + k0);
        cp16(base + Q_ALO + dA0, pA0l + k0);
        cp16(base + dA1,         pA1h + k0);
        cp16(base + Q_ALO + dA1, pA1l + k0);
        cp16(base + Q_BHI + dB,  pBh + k0);
        cp16(base + Q_BLO + dB,  pBl + k0);
        CP_COMMIT();
    };

    const uint32_t aOff =
        (uint32_t)((wm * 16 + (lane & 15)) * 48 + (lane >> 4) * 16);
    uint32_t bOff[2];
#pragma unroll
    for (int g = 0; g < 2; ++g)
        bOff[g] = (uint32_t)((g * 16 + (lane & 7) + ((lane >> 4) & 1) * 8) * 48 +
                             ((lane >> 3) & 1) * 16);

    issue(0); issue(1);
    for (int st = 0; st < 4; ++st) {
        if (st < 3) { CP_WAIT1(); } else { CP_WAIT0(); }
        __syncthreads();
        const uint32_t base = sb + (st % 3) * Q_STAGE;
#pragma unroll
        for (int sub = 0; sub < 2; ++sub) {
            uint32_t ah[4], al[4];
            ldm_x4(ah, base + sub * Q_SUBA + aOff);
            ldm_x4(al, base + Q_ALO + sub * Q_SUBA + aOff);
#pragma unroll
            for (int g = 0; g < 2; ++g) {
                uint32_t bh[4], bl[4];
                ldm_x4(bh, base + Q_BHI + sub * Q_SUBB + bOff[g]);
                ldm_x4(bl, base + Q_BLO + sub * Q_SUBB + bOff[g]);
#pragma unroll
                for (int nf = 0; nf < 2; ++nf) {
                    float* a4 = acc[g * 2 + nf];
                    mma_bf16(a4, ah, bh + 2 * nf);
                    mma_bf16(a4, ah, bl + 2 * nf);
                    mma_bf16(a4, al, bh + 2 * nf);
                }
            }
        }
        if (st < 2) issue(st + 2);
    }
}

// Store this CTA's partial tile (plain STG, no atomics) into bank B.
__device__ __forceinline__ void store_partial(float acc[4][4], int rowBase,
                                              int colBase, float* B) {
    const int lane = threadIdx.x & 31, wm = threadIdx.x >> 5;
#pragma unroll
    for (int g = 0; g < 2; ++g)
#pragma unroll
        for (int nf = 0; nf < 2; ++nf)
#pragma unroll
            for (int h = 0; h < 2; ++h) {
                int r = rowBase + wm * 16 + (lane >> 2) + h * 8;
                int c = colBase + g * 16 + nf * 8 + (lane & 3) * 2;
                float2 v = make_float2(acc[g * 2 + nf][h * 2 + 0],
                                       acc[g * 2 + nf][h * 2 + 1]);
                *(float2*)&B[r * NN + c] = v;
            }
}

// Sum 4 fwd banks for 4 consecutive columns at (r, c).
__device__ __forceinline__ float4 sum_banks4(int off) {
    float4 s = make_float4(0.f, 0.f, 0.f, 0.f);
#pragma unroll
    for (int z = 0; z < 4; ++z) {
        float4 a = *(const float4*)&g_Fb[z][off];
        s.x += a.x; s.y += a.y; s.z += a.z; s.w += a.w;
    }
    return s;
}

// ---------------------------------------------------------------------------
// Prep: split X/W2, transpose+split W1->W1T, W2->W2T; task 4: seed out with b3
// ---------------------------------------------------------------------------
__global__ void k_prep(const float* __restrict__ X, const float* __restrict__ W1,
                       const float* __restrict__ W2, const float* __restrict__ b3,
                       float* __restrict__ out) {
    __shared__ float ts[32][33];
    const int task = blockIdx.y;
    const int t = threadIdx.y * 32 + threadIdx.x;
    if (task == 4) {
        if (blockIdx.x == 0 && t < 128) {
            float b = b3[0];
            ((float4*)out)[t] = make_float4(b, b, b, b);
        }
        return;
    }
    const int tr = (blockIdx.x >> 4) * 32, tc = (blockIdx.x & 15) * 32;
    const int tx = threadIdx.x, ty = threadIdx.y;
    const float* src;
    bf16 *dhi, *dlo;
    bool trans;
    switch (task) {
        case 0:  src = X;  dhi = g_Xhi;   dlo = g_Xlo;   trans = false; break;
        case 1:  src = W1; dhi = g_W1Thi; dlo = g_W1Tlo; trans = true;  break;
        case 2:  src = W2; dhi = g_W2Thi; dlo = g_W2Tlo; trans = true;  break;
        default: src = W2; dhi = g_W2hi;  dlo = g_W2lo;  trans = false; break;
    }
    if (!trans) {
#pragma unroll
        for (int k = 0; k < 4; ++k) {
            int r = tr + ty + k * 8, c = tc + tx;
            split_store(dhi, dlo, r * NN + c, src[r * NN + c]);
        }
    } else {
#pragma unroll
        for (int k = 0; k < 4; ++k)
            ts[ty + k * 8][tx] = src[(tr + ty + k * 8) * NN + tc + tx];
        __syncthreads();
#pragma unroll
        for (int k = 0; k < 4; ++k) {
            int orow = tc + ty + k * 8, ocol = tr + tx;
            split_store(dhi, dlo, orow * NN + ocol, ts[tx][ty + k * 8]);
        }
    }
}

// ---------------------------------------------------------------------------
// FWD GEMMs: grid (16 nTiles, 8 mTiles, 4 kQuarters), 128 threads.
// Partial -> bank z; last CTA per tile: fused epilogue over 64x32 region.
// ---------------------------------------------------------------------------
__global__ void __launch_bounds__(128) k_fwd1(const float* __restrict__ b1) {
    extern __shared__ char dsm[];
    const uint32_t sb = smem_u32(dsm);
    const int rowBase = blockIdx.y * 64, colBase = blockIdx.x * 32;
    float acc[4][4] = {};
    mainloop_q(g_Xhi, g_Xlo, g_W1Thi, g_W1Tlo, rowBase, colBase,
               blockIdx.z * 128, sb, acc);
    store_partial(acc, rowBase, colBase, g_Fb[blockIdx.z]);
    const int tile = blockIdx.y * 16 + blockIdx.x;
    if (!last_of(&g_CntF[tile], 4)) return;
    const int t = threadIdx.x;
    const int r = rowBase + (t >> 1);
    const int c0 = colBase + (t & 1) * 16;
#pragma unroll
    for (int q = 0; q < 4; ++q) {
        float4 s = sum_banks4(r * NN + c0 + q * 4);
        float sv[4] = {s.x, s.y, s.z, s.w};
#pragma unroll
        for (int e = 0; e < 4; ++e) {
            int c = c0 + q * 4 + e;
            float hv = fmaxf(sv[e] + b1[c], 0.f);
            split_store(g_H1hi, g_H1lo, r * NN + c, hv);
        }
    }
    if (t == 0) g_CntF[tile] = 0;
}

__global__ void __launch_bounds__(128) k_fwd2(const float* __restrict__ b2,
                                              const float* __restrict__ w3,
                                              float* __restrict__ out) {
    extern __shared__ char dsm[];
    const uint32_t sb = smem_u32(dsm);
    const int rowBase = blockIdx.y * 64, colBase = blockIdx.x * 32;
    float acc[4][4] = {};
    mainloop_q(g_H1hi, g_H1lo, g_W2Thi, g_W2Tlo, rowBase, colBase,
               blockIdx.z * 128, sb, acc);
    store_partial(acc, rowBase, colBase, g_Fb[blockIdx.z]);
    const int tile = blockIdx.y * 16 + blockIdx.x;
    if (!last_of(&g_CntF[tile], 4)) return;
    const int t = threadIdx.x;
    const int r = rowBase + (t >> 1);
    const int c0 = colBase + (t & 1) * 16;
    float sdot = 0.f;
#pragma unroll
    for (int q = 0; q < 4; ++q) {
        float4 s = sum_banks4(r * NN + c0 + q * 4);
        float sv[4] = {s.x, s.y, s.z, s.w};
#pragma unroll
        for (int e = 0; e < 4; ++e) {
            int c = c0 + q * 4 + e;
            float z = sv[e] + b2[c];
            float hv = fmaxf(z, 0.f);
            int off = r * NN + c;
            split_store(g_H2hi, g_H2lo, off, hv);
            float wj = w3[c];
            float g = (z > 0.f) ? wj : 0.f;
            split_store(g_G2hi, g_G2lo, off, g);
            sdot += hv * wj;
        }
    }
    // threads t and t^1 share row r
    sdot += __shfl_xor_sync(0xffffffffu, sdot, 1);
    if ((t & 1) == 0) red_add(out + r, sdot);
    if (t == 0) g_CntF[tile] = 0;
}

__global__ void __launch_bounds__(128) k_g1() {
    extern __shared__ char dsm[];
    const uint32_t sb = smem_u32(dsm);
    const int rowBase = blockIdx.y * 64, colBase = blockIdx.x * 32;
    float acc[4][4] = {};
    mainloop_q(g_G2hi, g_G2lo, g_W2hi, g_W2lo, rowBase, colBase,
               blockIdx.z * 128, sb, acc);
    store_partial(acc, rowBase, colBase, g_Fb[blockIdx.z]);
    const int tile = blockIdx.y * 16 + blockIdx.x;
    if (!last_of(&g_CntF[tile], 4)) return;
    const int t = threadIdx.x;
    const int r = rowBase + (t >> 1);
    const int c0 = colBase + (t & 1) * 16;
#pragma unroll
    for (int q = 0; q < 4; ++q) {
        float4 s = sum_banks4(r * NN + c0 + q * 4);
        float sv[4] = {s.x, s.y, s.z, s.w};
#pragma unroll
        for (int e = 0; e < 4; ++e) {
            int c = c0 + q * 4 + e;
            int off = r * NN + c;
            float m = (__bfloat162float(g_H1hi[off]) > 0.f) ? sv[e] : 0.f;
            split_store(g_G1hi, g_G1lo, off, m);
        }
    }
    if (t == 0) g_CntF[tile] = 0;
}

// ---------------------------------------------------------------------------
// GRAM: lower-triangle 64x32 blocks (72) x 5 matrices x 4 kQuarters.
// Partials -> g_GPb[matrix*4+z]; 20th CTA per tile combines + mirrors.
// ---------------------------------------------------------------------------
__device__ __forceinline__ void tri72(int L, int& rb, int& cb) {
    int r = 0, c = L;
    while (c >= 2 * r + 2) { c -= 2 * r + 2; ++r; }
    rb = r; cb = c;
}

__global__ void __launch_bounds__(128) k_gram(float* __restrict__ gram) {
    extern __shared__ char dsm[];
    const uint32_t sb = smem_u32(dsm);
    int rb, cb;
    tri72(blockIdx.x, rb, cb);
    const int m = blockIdx.y, z = blockIdx.z;
    const bf16 *Mh, *Ml;
    switch (m) {
        case 0:  Mh = g_Xhi;  Ml = g_Xlo;  break;
        case 1:  Mh = g_H1hi; Ml = g_H1lo; break;
        case 2:  Mh = g_H2hi; Ml = g_H2lo; break;
        case 3:  Mh = g_G1hi; Ml = g_G1lo; break;
        default: Mh = g_G2hi; Ml = g_G2lo; break;
    }
    const int rowBase = rb * 64, colBase = cb * 32;
    float acc[4][4] = {};
    mainloop_q(Mh, Ml, Mh, Ml, rowBase, colBase, z * 128, sb, acc);
    store_partial(acc, rowBase, colBase, g_GPb[m * 4 + z]);
    if (!last_of(&g_CntG[blockIdx.x], 20)) return;
    const int t = threadIdx.x;
    const int r = rowBase + (t >> 1);
    const int c0 = colBase + (t & 1) * 16;
#pragma unroll
    for (int q = 0; q < 4; ++q) {
        int off4 = r * NN + c0 + q * 4;
        float sm[5][4];
#pragma unroll
        for (int mm = 0; mm < 5; ++mm) {
            float4 s = make_float4(0.f, 0.f, 0.f, 0.f);
#pragma unroll
            for (int zz = 0; zz < 4; ++zz) {
                float4 a = *(const float4*)&g_GPb[mm * 4 + zz][off4];
                s.x += a.x; s.y += a.y; s.z += a.z; s.w += a.w;
            }
            sm[mm][0] = s.x; sm[mm][1] = s.y; sm[mm][2] = s.z; sm[mm][3] = s.w;
        }
#pragma unroll
        for (int e = 0; e < 4; ++e) {
            int j = c0 + q * 4 + e;
            if (j > r) continue;
            float g = 1.f + sm[2][e] + sm[4][e] * (1.f + sm[1][e]) +
                      sm[3][e] * (1.f + sm[0][e]);
            gram[r * NN + j] = g;
            gram[j * NN + r] = g;
        }
    }
    if (t == 0) g_CntG[blockIdx.x] = 0;
}

// ---------------------------------------------------------------------------
// Launch (5 kernels)
// ---------------------------------------------------------------------------
extern "C" void kernel_launch(void* const* d_in, const int* in_sizes, int n_in,
                              void* d_out, int out_size) {
    const float* x  = (const float*)d_in[0];
    const float* W1 = (const float*)d_in[1];
    const float* b1 = (const float*)d_in[2];
    const float* W2 = (const float*)d_in[3];
    const float* b2 = (const float*)d_in[4];
    const float* w3 = (const float*)d_in[5];
    const float* b3 = (const float*)d_in[6];

    float* out  = (float*)d_out;       // [512]
    float* gram = (float*)d_out + NN;  // [512 x 512]

    cudaFuncSetAttribute(k_fwd1, cudaFuncAttributeMaxDynamicSharedMemorySize, Q_SMEM);
    cudaFuncSetAttribute(k_fwd2, cudaFuncAttributeMaxDynamicSharedMemorySize, Q_SMEM);
    cudaFuncSetAttribute(k_g1,   cudaFuncAttributeMaxDynamicSharedMemorySize, Q_SMEM);
    cudaFuncSetAttribute(k_gram, cudaFuncAttributeMaxDynamicSharedMemorySize, Q_SMEM);

    k_prep<<<dim3(256, 5), dim3(32, 8)>>>(x, W1, W2, b3, out);
    k_fwd1<<<dim3(16, 8, 4), 128, Q_SMEM>>>(b1);
    k_fwd2<<<dim3(16, 8, 4), 128, Q_SMEM>>>(b2, w3, out);
    k_g1<<<dim3(16, 8, 4), 128, Q_SMEM>>>();
    k_gram<<<dim3(72, 5, 4), 128, Q_SMEM>>>(gram);
}

// round 12
// speedup vs baseline: 1.4649x; 1.4649x over previous
#include <cuda_runtime.h>
#include <cuda_bf16.h>
#include <cstdint>

#define NN 512
using bf16 = __nv_bfloat16;

// ---------------------------------------------------------------------------
// Device scratch (no allocation allowed)
// ---------------------------------------------------------------------------
#define DECLB(n) __device__ __align__(16) bf16 n[NN * NN]
DECLB(g_Xhi);   DECLB(g_Xlo);
DECLB(g_W1Thi); DECLB(g_W1Tlo);
DECLB(g_W2Thi); DECLB(g_W2Tlo);
DECLB(g_W2hi);  DECLB(g_W2lo);
DECLB(g_H1hi);  DECLB(g_H1lo);
DECLB(g_H2hi);  DECLB(g_H2lo);
DECLB(g_G1hi);  DECLB(g_G1lo);
DECLB(g_G2hi);  DECLB(g_G2lo);
__device__ __align__(16) float g_Fb[2][NN * NN];     // fwd k-split banks
__device__ __align__(16) float g_GPb[10][NN * NN];   // gram banks [m*2+z]
__device__ int g_CntF[64];   // fwd per-tile counters (self-resetting)
__device__ int g_CntG[36];   // gram per-tile counters (self-resetting)

// ---------------------------------------------------------------------------
// PTX helpers (base PTX only — valid on virtual target sm_103)
// ---------------------------------------------------------------------------
__device__ __forceinline__ uint32_t smem_u32(const void* p) {
    return (uint32_t)__cvta_generic_to_shared(p);
}
__device__ __forceinline__ void ldm_x4(uint32_t a[4], uint32_t addr) {
    asm volatile("ldmatrix.sync.aligned.m8n8.x4.shared.b16 {%0,%1,%2,%3}, [%4];"
                 : "=r"(a[0]), "=r"(a[1]), "=r"(a[2]), "=r"(a[3]) : "r"(addr));
}
__device__ __forceinline__ void mma_bf16(float c[4], const uint32_t a[4],
                                         const uint32_t b[2]) {
    asm volatile(
        "mma.sync.aligned.m16n8k16.row.col.f32.bf16.bf16.f32 "
        "{%0,%1,%2,%3}, {%4,%5,%6,%7}, {%8,%9}, {%0,%1,%2,%3};"
        : "+f"(c[0]), "+f"(c[1]), "+f"(c[2]), "+f"(c[3])
        : "r"(a[0]), "r"(a[1]), "r"(a[2]), "r"(a[3]), "r"(b[0]), "r"(b[1]));
}
__device__ __forceinline__ void cp16(uint32_t dst, const void* src) {
    asm volatile("cp.async.cg.shared.global [%0], [%1], 16;" :: "r"(dst), "l"(src));
}
__device__ __forceinline__ void red_add(float* p, float v) {
    asm volatile("red.global.add.f32 [%0], %1;" :: "l"(p), "f"(v) : "memory");
}
#define CP_COMMIT() asm volatile("cp.async.commit_group;" ::: "memory")
#define CP_WAIT0()  asm volatile("cp.async.wait_group 0;" ::: "memory")
#define CP_WAIT1()  asm volatile("cp.async.wait_group 1;" ::: "memory")

__device__ __forceinline__ void split_store(bf16* hi, bf16* lo, int off, float v) {
    bf16 h = __float2bfloat16(v);
    hi[off] = h;
    lo[off] = __float2bfloat16(v - __bfloat162float(h));
}

// Last-CTA-per-tile gate (every thread of the CTA must call).
__device__ __forceinline__ bool last_of(int* cnt, int target) {
    __threadfence();
    __shared__ int lastFlag;
    if (threadIdx.x == 0) lastFlag = (atomicAdd(cnt, 1) == target - 1) ? 1 : 0;
    __syncthreads();
    if (!lastFlag) return false;
    __threadfence();
    return true;
}

// ===========================================================================
// GEMM job: tile M=64, N=64, K=256 (8 k32 stages), 256 threads,
// 8 warps (4m x 2n), warp tile 16x32 => 4 m16n8 fragments (ILP 4).
// SMEM ring of 3 stages. Stage (bytes): Ahi[2][64][24h]@0, Alo@6144,
// Bhi@12288, Blo@18432. Stage stride 24576. Ring 73728 B.
// All 12 ldmatrix of a stage are batched before the 24 MMAs.
// ===========================================================================
constexpr int G_SUB   = 3072;
constexpr int G_ALO   = 6144;
constexpr int G_BHI   = 12288;
constexpr int G_BLO   = 18432;
constexpr int G_STAGE = 24576;
constexpr int G_SMEM  = 3 * G_STAGE;   // 73728

__device__ __forceinline__ void mainloop64(
    const bf16* __restrict__ Ahi, const bf16* __restrict__ Alo,
    const bf16* __restrict__ Bhi, const bf16* __restrict__ Blo,
    int rowBase, int colBase, int kBase, uint32_t sb, float acc[4][4])
{
    const int t = threadIdx.x;
    const int lane = t & 31, wid = t >> 5;
    const int wm = wid & 3, wn = wid >> 2;

    // cp.async mapping: 4 x 16B per thread (A-hi, A-lo, B-hi, B-lo)
    const int arow = t >> 2, ac = t & 3;
    const uint32_t dA = (uint32_t)((ac >> 1) * G_SUB + arow * 48 + (ac & 1) * 16);
    const bf16* pAh = Ahi + (rowBase + arow) * NN + kBase + ac * 8;
    const bf16* pAl = Alo + (rowBase + arow) * NN + kBase + ac * 8;
    const bf16* pBh = Bhi + (colBase + arow) * NN + kBase + ac * 8;
    const bf16* pBl = Blo + (colBase + arow) * NN + kBase + ac * 8;

    auto issue = [&](int stg) {
        const uint32_t base = sb + (stg % 3) * G_STAGE;
        const int k0 = stg * 32;
        cp16(base + dA,         pAh + k0);
        cp16(base + G_ALO + dA, pAl + k0);
        cp16(base + G_BHI + dA, pBh + k0);
        cp16(base + G_BLO + dA, pBl + k0);
        CP_COMMIT();
    };

    const uint32_t aOff =
        (uint32_t)((wm * 16 + (lane & 15)) * 48 + (lane >> 4) * 16);
    uint32_t bOff[2];
#pragma unroll
    for (int fn2 = 0; fn2 < 2; ++fn2)
        bOff[fn2] = (uint32_t)((wn * 32 + fn2 * 16 + (lane & 7) +
                                ((lane >> 4) & 1) * 8) * 48 +
                               ((lane >> 3) & 1) * 16);

    issue(0); issue(1);
    for (int st = 0; st < 8; ++st) {
        if (st < 7) { CP_WAIT1(); } else { CP_WAIT0(); }
        __syncthreads();
        const uint32_t base = sb + (st % 3) * G_STAGE;
        // Batch ALL fragment loads for both k16 sub-slices first.
        uint32_t ah[2][4], al[2][4], bh[2][2][4], bl[2][2][4];
#pragma unroll
        for (int sub = 0; sub < 2; ++sub) {
            ldm_x4(ah[sub], base + sub * G_SUB + aOff);
            ldm_x4(al[sub], base + G_ALO + sub * G_SUB + aOff);
            ldm_x4(bh[sub][0], base + G_BHI + sub * G_SUB + bOff[0]);
            ldm_x4(bl[sub][0], base + G_BLO + sub * G_SUB + bOff[0]);
            ldm_x4(bh[sub][1], base + G_BHI + sub * G_SUB + bOff[1]);
            ldm_x4(bl[sub][1], base + G_BLO + sub * G_SUB + bOff[1]);
        }
#pragma unroll
        for (int sub = 0; sub < 2; ++sub)
#pragma unroll
            for (int fn2 = 0; fn2 < 2; ++fn2)
#pragma unroll
                for (int nf = 0; nf < 2; ++nf) {
                    float* a4 = acc[fn2 * 2 + nf];
                    mma_bf16(a4, ah[sub], bh[sub][fn2] + 2 * nf);
                    mma_bf16(a4, ah[sub], bl[sub][fn2] + 2 * nf);
                    mma_bf16(a4, al[sub], bh[sub][fn2] + 2 * nf);
                }
        if (st < 6) issue(st + 2);
        else CP_COMMIT();
    }
}

// Store this CTA's partial 64x64 tile (plain STG) into bank B.
__device__ __forceinline__ void store_partial(float acc[4][4], int rowBase,
                                              int colBase, float* B) {
    const int lane = threadIdx.x & 31, wid = threadIdx.x >> 5;
    const int wm = wid & 3, wn = wid >> 2;
#pragma unroll
    for (int fn2 = 0; fn2 < 2; ++fn2)
#pragma unroll
        for (int nf = 0; nf < 2; ++nf)
#pragma unroll
            for (int h = 0; h < 2; ++h) {
                int r = rowBase + wm * 16 + (lane >> 2) + h * 8;
                int c = colBase + wn * 32 + fn2 * 16 + nf * 8 + (lane & 3) * 2;
                float2 v = make_float2(acc[fn2 * 2 + nf][h * 2 + 0],
                                       acc[fn2 * 2 + nf][h * 2 + 1]);
                *(float2*)&B[r * NN + c] = v;
            }
}

// Sum the 2 fwd banks, 4 consecutive columns at offset.
__device__ __forceinline__ float4 sum_fwd_banks(int off) {
    float4 a = *(const float4*)&g_Fb[0][off];
    float4 b = *(const float4*)&g_Fb[1][off];
    return make_float4(a.x + b.x, a.y + b.y, a.z + b.z, a.w + b.w);
}

// ---------------------------------------------------------------------------
// Prep: split X/W2, transpose+split W1->W1T, W2->W2T; task 4: seed out with b3
// ---------------------------------------------------------------------------
__global__ void k_prep(const float* __restrict__ X, const float* __restrict__ W1,
                       const float* __restrict__ W2, const float* __restrict__ b3,
                       float* __restrict__ out) {
    __shared__ float ts[32][33];
    const int task = blockIdx.y;
    const int t = threadIdx.y * 32 + threadIdx.x;
    if (task == 4) {
        if (blockIdx.x == 0 && t < 128) {
            float b = b3[0];
            ((float4*)out)[t] = make_float4(b, b, b, b);
        }
        return;
    }
    const int tr = (blockIdx.x >> 4) * 32, tc = (blockIdx.x & 15) * 32;
    const int tx = threadIdx.x, ty = threadIdx.y;
    const float* src;
    bf16 *dhi, *dlo;
    bool trans;
    switch (task) {
        case 0:  src = X;  dhi = g_Xhi;   dlo = g_Xlo;   trans = false; break;
        case 1:  src = W1; dhi = g_W1Thi; dlo = g_W1Tlo; trans = true;  break;
        case 2:  src = W2; dhi = g_W2Thi; dlo = g_W2Tlo; trans = true;  break;
        default: src = W2; dhi = g_W2hi;  dlo = g_W2lo;  trans = false; break;
    }
    if (!trans) {
#pragma unroll
        for (int k = 0; k < 4; ++k) {
            int r = tr + ty + k * 8, c = tc + tx;
            split_store(dhi, dlo, r * NN + c, src[r * NN + c]);
        }
    } else {
#pragma unroll
        for (int k = 0; k < 4; ++k)
            ts[ty + k * 8][tx] = src[(tr + ty + k * 8) * NN + tc + tx];
        __syncthreads();
#pragma unroll
        for (int k = 0; k < 4; ++k) {
            int orow = tc + ty + k * 8, ocol = tr + tx;
            split_store(dhi, dlo, orow * NN + ocol, ts[tx][ty + k * 8]);
        }
    }
}

// ---------------------------------------------------------------------------
// FWD GEMMs: grid (8 nTiles, 8 mTiles, 2 kHalves), 256 threads.
// Partial -> bank z; last CTA per tile sums banks + fused epilogue (64x64).
// Epilogue map: r = rowBase + t/4, c0 = colBase + (t%4)*16.
// ---------------------------------------------------------------------------
__global__ void __launch_bounds__(256) k_fwd1(const float* __restrict__ b1) {
    extern __shared__ char dsm[];
    const uint32_t sb = smem_u32(dsm);
    const int rowBase = blockIdx.y * 64, colBase = blockIdx.x * 64;
    float acc[4][4] = {};
    mainloop64(g_Xhi, g_Xlo, g_W1Thi, g_W1Tlo, rowBase, colBase,
               blockIdx.z * 256, sb, acc);
    store_partial(acc, rowBase, colBase, g_Fb[blockIdx.z]);
    const int tile = blockIdx.y * 8 + blockIdx.x;
    if (!last_of(&g_CntF[tile], 2)) return;
    const int t = threadIdx.x;
    const int r = rowBase + (t >> 2);
    const int c0 = colBase + (t & 3) * 16;
#pragma unroll
    for (int q = 0; q < 4; ++q) {
        float4 s = sum_fwd_banks(r * NN + c0 + q * 4);
        float sv[4] = {s.x, s.y, s.z, s.w};
#pragma unroll
        for (int e = 0; e < 4; ++e) {
            int c = c0 + q * 4 + e;
            float hv = fmaxf(sv[e] + b1[c], 0.f);
            split_store(g_H1hi, g_H1lo, r * NN + c, hv);
        }
    }
    if (t == 0) g_CntF[tile] = 0;
}

__global__ void __launch_bounds__(256) k_fwd2(const float* __restrict__ b2,
                                              const float* __restrict__ w3,
                                              float* __restrict__ out) {
    extern __shared__ char dsm[];
    const uint32_t sb = smem_u32(dsm);
    const int rowBase = blockIdx.y * 64, colBase = blockIdx.x * 64;
    float acc[4][4] = {};
    mainloop64(g_H1hi, g_H1lo, g_W2Thi, g_W2Tlo, rowBase, colBase,
               blockIdx.z * 256, sb, acc);
    store_partial(acc, rowBase, colBase, g_Fb[blockIdx.z]);
    const int tile = blockIdx.y * 8 + blockIdx.x;
    if (!last_of(&g_CntF[tile], 2)) return;
    const int t = threadIdx.x;
    const int r = rowBase + (t >> 2);
    const int c0 = colBase + (t & 3) * 16;
    float sdot = 0.f;
#pragma unroll
    for (int q = 0; q < 4; ++q) {
        float4 s = sum_fwd_banks(r * NN + c0 + q * 4);
        float sv[4] = {s.x, s.y, s.z, s.w};
#pragma unroll
        for (int e = 0; e < 4; ++e) {
            int c = c0 + q * 4 + e;
            float z = sv[e] + b2[c];
            float hv = fmaxf(z, 0.f);
            int off = r * NN + c;
            split_store(g_H2hi, g_H2lo, off, hv);
            float wj = w3[c];
            float g = (z > 0.f) ? wj : 0.f;
            split_store(g_G2hi, g_G2lo, off, g);
            sdot += hv * wj;
        }
    }
    // 4 threads (t, t^1, t^2, t^3) share row r — same 4-lane group of a warp
    sdot += __shfl_xor_sync(0xffffffffu, sdot, 1);
    sdot += __shfl_xor_sync(0xffffffffu, sdot, 2);
    if ((t & 3) == 0) red_add(out + r, sdot);
    if (t == 0) g_CntF[tile] = 0;
}

__global__ void __launch_bounds__(256) k_g1() {
    extern __shared__ char dsm[];
    const uint32_t sb = smem_u32(dsm);
    const int rowBase = blockIdx.y * 64, colBase = blockIdx.x * 64;
    float acc[4][4] = {};
    mainloop64(g_G2hi, g_G2lo, g_W2hi, g_W2lo, rowBase, colBase,
               blockIdx.z * 256, sb, acc);
    store_partial(acc, rowBase, colBase, g_Fb[blockIdx.z]);
    const int tile = blockIdx.y * 8 + blockIdx.x;
    if (!last_of(&g_CntF[tile], 2)) return;
    const int t = threadIdx.x;
    const int r = rowBase + (t >> 2);
    const int c0 = colBase + (t & 3) * 16;
#pragma unroll
    for (int q = 0; q < 4; ++q) {
        float4 s = sum_fwd_banks(r * NN + c0 + q * 4);
        float sv[4] = {s.x, s.y, s.z, s.w};
#pragma unroll
        for (int e = 0; e < 4; ++e) {
            int c = c0 + q * 4 + e;
            int off = r * NN + c;
            float m = (__bfloat162float(g_H1hi[off]) > 0.f) ? sv[e] : 0.f;
            split_store(g_G1hi, g_G1lo, off, m);
        }
    }
    if (t == 0) g_CntF[tile] = 0;
}

// ---------------------------------------------------------------------------
// GRAM: lower-triangle 64x64 blocks (36) x 5 matrices x 2 kHalves = 360 CTAs.
// Partials -> g_GPb[m*2+z]; 10th CTA per tile combines all + mirrors.
// ---------------------------------------------------------------------------
__device__ __forceinline__ void tri36(int L, int& rb, int& cb) {
    int r = 0;
    while (L >= r + 1) { L -= r + 1; ++r; }
    rb = r; cb = L;
}

__global__ void __launch_bounds__(256) k_gram(float* __restrict__ gram) {
    extern __shared__ char dsm[];
    const uint32_t sb = smem_u32(dsm);
    int rb, cb;
    tri36(blockIdx.x, rb, cb);
    const int m = blockIdx.y, z = blockIdx.z;
    const bf16 *Mh, *Ml;
    switch (m) {
        case 0:  Mh = g_Xhi;  Ml = g_Xlo;  break;
        case 1:  Mh = g_H1hi; Ml = g_H1lo; break;
        case 2:  Mh = g_H2hi; Ml = g_H2lo; break;
        case 3:  Mh = g_G1hi; Ml = g_G1lo; break;
        default: Mh = g_G2hi; Ml = g_G2lo; break;
    }
    const int rowBase = rb * 64, colBase = cb * 64;
    float acc[4][4] = {};
    mainloop64(Mh, Ml, Mh, Ml, rowBase, colBase, z * 256, sb, acc);
    store_partial(acc, rowBase, colBase, g_GPb[m * 2 + z]);
    if (!last_of(&g_CntG[blockIdx.x], 10)) return;
    const int t = threadIdx.x;
    const int r = rowBase + (t >> 2);
    const int c0 = colBase + (t & 3) * 16;
#pragma unroll
    for (int q = 0; q < 4; ++q) {
        int off4 = r * NN + c0 + q * 4;
        float sm[5][4];
#pragma unroll
        for (int mm = 0; mm < 5; ++mm) {
            float4 a = *(const float4*)&g_GPb[mm * 2 + 0][off4];
            float4 b = *(const float4*)&g_GPb[mm * 2 + 1][off4];
            sm[mm][0] = a.x + b.x; sm[mm][1] = a.y + b.y;
            sm[mm][2] = a.z + b.z; sm[mm][3] = a.w + b.w;
        }
#pragma unroll
        for (int e = 0; e < 4; ++e) {
            int j = c0 + q * 4 + e;
            if (j > r) continue;
            float g = 1.f + sm[2][e] + sm[4][e] * (1.f + sm[1][e]) +
                      sm[3][e] * (1.f + sm[0][e]);
            gram[r * NN + j] = g;
            gram[j * NN + r] = g;
        }
    }
    if (t == 0) g_CntG[blockIdx.x] = 0;
}

// ---------------------------------------------------------------------------
// Launch (5 kernels)
// ---------------------------------------------------------------------------
extern "C" void kernel_launch(void* const* d_in, const int* in_sizes, int n_in,
                              void* d_out, int out_size) {
    const float* x  = (const float*)d_in[0];
    const float* W1 = (const float*)d_in[1];
    const float* b1 = (const float*)d_in[2];
    const float* W2 = (const float*)d_in[3];
    const float* b2 = (const float*)d_in[4];
    const float* w3 = (const float*)d_in[5];
    const float* b3 = (const float*)d_in[6];

    float* out  = (float*)d_out;       // [512]
    float* gram = (float*)d_out + NN;  // [512 x 512]

    cudaFuncSetAttribute(k_fwd1, cudaFuncAttributeMaxDynamicSharedMemorySize, G_SMEM);
    cudaFuncSetAttribute(k_fwd2, cudaFuncAttributeMaxDynamicSharedMemorySize, G_SMEM);
    cudaFuncSetAttribute(k_g1,   cudaFuncAttributeMaxDynamicSharedMemorySize, G_SMEM);
    cudaFuncSetAttribute(k_gram, cudaFuncAttributeMaxDynamicSharedMemorySize, G_SMEM);

    k_prep<<<dim3(256, 5), dim3(32, 8)>>>(x, W1, W2, b3, out);
    k_fwd1<<<dim3(8, 8, 2), 256, G_SMEM>>>(b1);
    k_fwd2<<<dim3(8, 8, 2), 256, G_SMEM>>>(b2, w3, out);
    k_g1<<<dim3(8, 8, 2), 256, G_SMEM>>>();
    k_gram<<<dim3(36, 5, 2), 256, G_SMEM>>>(gram);
}